// round 4
// baseline (speedup 1.0000x reference)
#include <cuda_runtime.h>
#include <cuda_bf16.h>
#include <cstdint>

#define N_VAR 4194304
#define M_CHK 2097152
#define DC 10
#define CBLK 256
#define NTILES (M_CHK / CBLK)          // 8192
#define ADJ_INTS (CBLK * DC)           // 2560 ints per tile
#define ADJ_BYTES (ADJ_INTS * 4)       // 10240 B per tile
#define GRID_PERSIST 1184              // 148 SMs * 8 blocks

// scratch (device globals: allocation-free)
__device__ float g_b0[N_VAR];
__device__ float g_b1[N_VAR];
__device__ float g_b2[N_VAR];

__device__ __forceinline__ uint32_t smem_u32(const void* p) {
    uint32_t a;
    asm("{ .reg .u64 t; cvta.to.shared.u64 t, %1; cvt.u32.u64 %0, t; }" : "=r"(a) : "l"(p));
    return a;
}

__device__ __forceinline__ void mbar_init(uint32_t mbar, uint32_t cnt) {
    asm volatile("mbarrier.init.shared.b64 [%0], %1;" :: "r"(mbar), "r"(cnt) : "memory");
}
__device__ __forceinline__ void tma_1d(uint32_t sdst, const void* gsrc, uint32_t bytes,
                                       uint32_t mbar) {
    asm volatile("mbarrier.arrive.expect_tx.shared.b64 _, [%0], %1;"
                 :: "r"(mbar), "r"(bytes) : "memory");
    asm volatile(
        "cp.async.bulk.shared::cta.global.mbarrier::complete_tx::bytes [%0], [%1], %2, [%3];"
        :: "r"(sdst), "l"(gsrc), "r"(bytes), "r"(mbar) : "memory");
}
__device__ __forceinline__ void mbar_wait(uint32_t mbar, uint32_t parity) {
    uint32_t done;
    asm volatile(
        "{\n\t.reg .pred p;\n\t"
        "mbarrier.try_wait.parity.acquire.cta.shared::cta.b64 p, [%1], %2;\n\t"
        "selp.b32 %0, 1, 0, p;\n\t}"
        : "=r"(done) : "r"(mbar), "r"(parity) : "memory");
    while (!done) {
        asm volatile(
            "{\n\t.reg .pred p;\n\t"
            "mbarrier.try_wait.parity.acquire.cta.shared::cta.b64 p, [%1], %2, 0x989680;\n\t"
            "selp.b32 %0, 1, 0, p;\n\t}"
            : "=r"(done) : "r"(mbar), "r"(parity) : "memory");
    }
}

// seed accumulator: acc = scale*llr0 - v2c_prev  (scale = 1 mid, 2 for final/out)
__global__ void bp_seed(const float* __restrict__ llr0,
                        const float* __restrict__ v2c_prev,
                        float* __restrict__ acc, float scale) {
    int i = blockIdx.x * blockDim.x + threadIdx.x;
    float4 l = reinterpret_cast<const float4*>(llr0)[i];
    float4 p = reinterpret_cast<const float4*>(v2c_prev)[i];
    float4 s = make_float4(fmaf(scale, l.x, -p.x), fmaf(scale, l.y, -p.y),
                           fmaf(scale, l.z, -p.z), fmaf(scale, l.w, -p.w));
    reinterpret_cast<float4*>(acc)[i] = s;
}

// Persistent check-node kernel: grid-stride over tiles with double-buffered
// TMA prefetch of adjacency. Gather src, min-sum, scatter-add into pre-seeded dst.
__global__ void __launch_bounds__(CBLK) bp_check(const int* __restrict__ adj,
                                                 const float* __restrict__ gamma_p,
                                                 const float* __restrict__ src,
                                                 float* __restrict__ dst) {
    __shared__ __align__(16) int s_adj[2][ADJ_INTS];
    __shared__ __align__(8) unsigned long long s_mbar[2];

    const int tid = threadIdx.x;
    const uint32_t mb0 = smem_u32(&s_mbar[0]);
    const uint32_t mb1 = smem_u32(&s_mbar[1]);

    if (tid == 0) { mbar_init(mb0, 1); mbar_init(mb1, 1); }
    __syncthreads();

    int tile = blockIdx.x;
    if (tid == 0 && tile < NTILES) {
        tma_1d(smem_u32(s_adj[0]), adj + (size_t)tile * ADJ_INTS, ADJ_BYTES, mb0);
    }

    const float gamma = __ldg(gamma_p);
    const float vlast = __ldg(&src[N_VAR - 1]);  // all padded (-1) slots wrap here

    int buf = 0;
    uint32_t ph0 = 0, ph1 = 0;

    for (; tile < NTILES; tile += GRID_PERSIST) {
        // wait for current buffer
        if (buf == 0) { mbar_wait(mb0, ph0); ph0 ^= 1; }
        else          { mbar_wait(mb1, ph1); ph1 ^= 1; }

        int idx[DC];
        #pragma unroll
        for (int j = 0; j < DC; j++) idx[j] = s_adj[buf][tid * DC + j];

        // all threads have consumed this buffer's smem and (by program order)
        // finished with the other buffer from the previous round
        __syncthreads();

        // prefetch next tile into the other buffer
        int next = tile + GRID_PERSIST;
        if (tid == 0 && next < NTILES) {
            uint32_t nb = (buf == 0) ? mb1 : mb0;
            tma_1d(smem_u32(s_adj[buf ^ 1]), adj + (size_t)next * ADJ_INTS, ADJ_BYTES, nb);
        }

        float mag = __int_as_float(0x7f800000);  // +inf
        unsigned sgn = 0u;
        #pragma unroll
        for (int j = 0; j < DC; j++) {
            float v = (idx[j] >= 0) ? __ldg(&src[idx[j]]) : vlast;
            sgn ^= (__float_as_uint(v + 1e-12f) & 0x80000000u);
            mag = fminf(mag, fabsf(v));
        }
        float c2v = __uint_as_float(__float_as_uint(gamma * mag) ^ sgn);

        #pragma unroll
        for (int j = 0; j < DC; j++) {
            if (idx[j] >= 0) atomicAdd(&dst[idx[j]], c2v);
        }

        buf ^= 1;
    }
}

extern "C" void kernel_launch(void* const* d_in, const int* in_sizes, int n_in,
                              void* d_out, int out_size) {
    const float* llr0  = (const float*)d_in[0];
    const float* gamma = (const float*)d_in[1];
    const int*   adj   = (const int*)d_in[2];
    float* out = (float*)d_out;

    float *b0, *b1, *b2;
    cudaGetSymbolAddress((void**)&b0, g_b0);
    cudaGetSymbolAddress((void**)&b1, g_b1);
    cudaGetSymbolAddress((void**)&b2, g_b2);

    const int vec_blocks = N_VAR / 4 / 256;

    // n_iter = 5. Iter 1 is exact identity (v2c1 = llr0). Remaining 4 rounds:
    // accumulators pre-seeded with (llr0 - v2c_prev) so check's atomics produce
    // v2c_next in place; final accumulator is d_out seeded with (2*llr0 - v2c_4).
    cudaMemsetAsync(b0, 0, (size_t)N_VAR * sizeof(float));       // seed iter2: 0
    bp_check<<<GRID_PERSIST, CBLK>>>(adj, gamma, llr0, b0);      // b0 = v2c_2
    bp_seed<<<vec_blocks, 256>>>(llr0, b0, b1, 1.f);             // b1 = llr0 - v2c_2
    bp_check<<<GRID_PERSIST, CBLK>>>(adj, gamma, b0, b1);        // b1 = v2c_3
    bp_seed<<<vec_blocks, 256>>>(llr0, b1, b2, 1.f);             // b2 = llr0 - v2c_3
    bp_check<<<GRID_PERSIST, CBLK>>>(adj, gamma, b1, b2);        // b2 = v2c_4
    bp_seed<<<vec_blocks, 256>>>(llr0, b2, out, 2.f);            // out = 2*llr0 - v2c_4
    bp_check<<<GRID_PERSIST, CBLK>>>(adj, gamma, b2, out);       // out = llr0 + v2c_5
}

// round 5
// speedup vs baseline: 1.1017x; 1.1017x over previous
#include <cuda_runtime.h>
#include <cuda_bf16.h>
#include <cstdint>

#define N_VAR 4194304
#define M_CHK 2097152
#define DC 10
#define CBLK 256
#define ADJ_BYTES (CBLK * DC * 4)

// scratch (device globals: allocation-free)
__device__ float g_b0[N_VAR];
__device__ float g_b1[N_VAR];
__device__ float g_b2[N_VAR];

__device__ __forceinline__ uint32_t smem_u32(const void* p) {
    uint32_t a;
    asm("{ .reg .u64 t; cvta.to.shared.u64 t, %1; cvt.u32.u64 %0, t; }" : "=r"(a) : "l"(p));
    return a;
}

// seed accumulator: acc = scale*llr0 - v2c_prev  (scale = 1 mid, 2 for final/out)
__global__ void __launch_bounds__(512) bp_seed(const float* __restrict__ llr0,
                                               const float* __restrict__ v2c_prev,
                                               float* __restrict__ acc, float scale) {
    int i = blockIdx.x * blockDim.x + threadIdx.x;
    float4 l = __ldcs(&reinterpret_cast<const float4*>(llr0)[i]);
    float4 p = __ldcs(&reinterpret_cast<const float4*>(v2c_prev)[i]);
    float4 s = make_float4(fmaf(scale, l.x, -p.x), fmaf(scale, l.y, -p.y),
                           fmaf(scale, l.z, -p.z), fmaf(scale, l.w, -p.w));
    reinterpret_cast<float4*>(acc)[i] = s;
}

// check-node update: gather src (L2-only, no L1 allocate), min-sum,
// scatter-add into pre-seeded dst. adj rows staged to smem via TMA.
__global__ void __launch_bounds__(CBLK) bp_check(const int* __restrict__ adj,
                                                 const float* __restrict__ gamma_p,
                                                 const float* __restrict__ src,
                                                 float* __restrict__ dst) {
    __shared__ __align__(16) int s_adj[CBLK * DC];
    __shared__ __align__(8) unsigned long long s_mbar;

    const int tid = threadIdx.x;
    uint32_t mbar = smem_u32(&s_mbar);
    uint32_t sdst = smem_u32(s_adj);

    if (tid == 0) {
        asm volatile("mbarrier.init.shared.b64 [%0], 1;" :: "r"(mbar) : "memory");
    }
    __syncthreads();
    if (tid == 0) {
        asm volatile("mbarrier.arrive.expect_tx.shared.b64 _, [%0], %1;"
                     :: "r"(mbar), "r"((uint32_t)ADJ_BYTES) : "memory");
        const int* gsrc = adj + (size_t)blockIdx.x * (CBLK * DC);
        asm volatile(
            "cp.async.bulk.shared::cta.global.mbarrier::complete_tx::bytes "
            "[%0], [%1], %2, [%3];"
            :: "r"(sdst), "l"(gsrc), "r"((uint32_t)ADJ_BYTES), "r"(mbar) : "memory");
    }
    // wait for TMA completion (phase 0)
    {
        uint32_t done;
        asm volatile(
            "{\n\t.reg .pred p;\n\t"
            "mbarrier.try_wait.parity.acquire.cta.shared::cta.b64 p, [%1], 0;\n\t"
            "selp.b32 %0, 1, 0, p;\n\t}"
            : "=r"(done) : "r"(mbar) : "memory");
        while (!done) {
            asm volatile(
                "{\n\t.reg .pred p;\n\t"
                "mbarrier.try_wait.parity.acquire.cta.shared::cta.b64 p, [%1], 0, 0x989680;\n\t"
                "selp.b32 %0, 1, 0, p;\n\t}"
                : "=r"(done) : "r"(mbar) : "memory");
        }
    }

    const float gamma = __ldg(gamma_p);
    const float vlast = __ldg(&src[N_VAR - 1]);  // all padded (-1) slots wrap here

    int idx[DC];
    #pragma unroll
    for (int j = 0; j < DC; j++) idx[j] = s_adj[tid * DC + j];

    float mag = __int_as_float(0x7f800000);  // +inf
    unsigned sgn = 0u;
    #pragma unroll
    for (int j = 0; j < DC; j++) {
        // ld.global.cg: L2-cached, no L1 line allocation (random, zero-reuse)
        float v = (idx[j] >= 0) ? __ldcg(&src[idx[j]]) : vlast;
        sgn ^= (__float_as_uint(v + 1e-12f) & 0x80000000u);
        mag = fminf(mag, fabsf(v));
    }
    float c2v = __uint_as_float(__float_as_uint(gamma * mag) ^ sgn);

    #pragma unroll
    for (int j = 0; j < DC; j++) {
        if (idx[j] >= 0) atomicAdd(&dst[idx[j]], c2v);
    }
}

extern "C" void kernel_launch(void* const* d_in, const int* in_sizes, int n_in,
                              void* d_out, int out_size) {
    const float* llr0  = (const float*)d_in[0];
    const float* gamma = (const float*)d_in[1];
    const int*   adj   = (const int*)d_in[2];
    float* out = (float*)d_out;

    float *b0, *b1, *b2;
    cudaGetSymbolAddress((void**)&b0, g_b0);
    cudaGetSymbolAddress((void**)&b1, g_b1);
    cudaGetSymbolAddress((void**)&b2, g_b2);

    const int vec_blocks = N_VAR / 4 / 512;
    const int chk_blocks = M_CHK / CBLK;

    // n_iter = 5. Iter 1 is exact identity (v2c1 = llr0). Remaining 4 rounds:
    // accumulators pre-seeded with (llr0 - v2c_prev) so check's atomics produce
    // v2c_next in place; final accumulator is d_out seeded with (2*llr0 - v2c_4).
    cudaMemsetAsync(b0, 0, (size_t)N_VAR * sizeof(float));       // seed iter2: 0
    bp_check<<<chk_blocks, CBLK>>>(adj, gamma, llr0, b0);        // b0 = v2c_2
    bp_seed<<<vec_blocks, 512>>>(llr0, b0, b1, 1.f);             // b1 = llr0 - v2c_2
    bp_check<<<chk_blocks, CBLK>>>(adj, gamma, b0, b1);          // b1 = v2c_3
    bp_seed<<<vec_blocks, 512>>>(llr0, b1, b2, 1.f);             // b2 = llr0 - v2c_3
    bp_check<<<chk_blocks, CBLK>>>(adj, gamma, b1, b2);          // b2 = v2c_4
    bp_seed<<<vec_blocks, 512>>>(llr0, b2, out, 2.f);            // out = 2*llr0 - v2c_4
    bp_check<<<chk_blocks, CBLK>>>(adj, gamma, b2, out);         // out = llr0 + v2c_5
}